// round 7
// baseline (speedup 1.0000x reference)
#include <cuda_runtime.h>
#include <cstdint>

// z = sum_{p,q,r} C[p*9+q*3+r] * u0_p * u1_q * u2_r,  u_i = (1, cos x_i, sin x_i)
__device__ float d_C[27];

// ---------------------------------------------------------------------------
// Kernel 1: build the 27 trilinear coefficients from q_weights (18 floats).
// ---------------------------------------------------------------------------
__global__ void build_coeffs(const float* __restrict__ qw) {
    __shared__ float Ure[8][8];
    __shared__ float Uim[8][8];
    __shared__ float A[8][8];

    int t = threadIdx.x;

    if (t < 8) {
        const int j = t;
        float sr[8], si[8];
        #pragma unroll
        for (int m = 0; m < 8; m++) { sr[m] = 0.f; si[m] = 0.f; }
        sr[j] = 1.0f;

        for (int l = 0; l < 3; l++) {
            #pragma unroll
            for (int q = 0; q < 3; q++) {
                float ty = qw[(l * 3 + q) * 2 + 0];
                float tz = qw[(l * 3 + q) * 2 + 1];
                int bit = 4 >> q;

                float c, s;
                __sincosf(0.5f * ty, &s, &c);
                #pragma unroll
                for (int m = 0; m < 8; m++) {
                    if (m & bit) continue;
                    int m1 = m | bit;
                    float ar = sr[m],  ai = si[m];
                    float br = sr[m1], bi = si[m1];
                    sr[m]  = c * ar - s * br;  si[m]  = c * ai - s * bi;
                    sr[m1] = s * ar + c * br;  si[m1] = s * ai + c * bi;
                }

                float cz, sz;
                __sincosf(0.5f * tz, &sz, &cz);
                #pragma unroll
                for (int m = 0; m < 8; m++) {
                    float ar = sr[m], ai = si[m];
                    if (m & bit) { sr[m] = cz * ar - sz * ai; si[m] = cz * ai + sz * ar; }
                    else         { sr[m] = cz * ar + sz * ai; si[m] = cz * ai - sz * ar; }
                }
            }
            #pragma unroll
            for (int m = 4; m < 6; m++) {           // CNOT01: swap (4,6),(5,7)
                int m1 = m | 2; float tmp;
                tmp = sr[m]; sr[m] = sr[m1]; sr[m1] = tmp;
                tmp = si[m]; si[m] = si[m1]; si[m1] = tmp;
            }
            #pragma unroll
            for (int m = 2; m < 8; m += 4) {        // CNOT12: swap (2,3),(6,7)
                int m1 = m | 1; float tmp;
                tmp = sr[m]; sr[m] = sr[m1]; sr[m1] = tmp;
                tmp = si[m]; si[m] = si[m1]; si[m1] = tmp;
            }
        }
        #pragma unroll
        for (int m = 0; m < 8; m++) { Ure[m][j] = sr[m]; Uim[m][j] = si[m]; }
    }
    __syncthreads();

    if (t < 64) {
        int j = t >> 3, k = t & 7;
        float a = 0.f;
        #pragma unroll
        for (int m = 0; m < 8; m++) {
            float sgn = (m & 4) ? -1.f : 1.f;
            a += sgn * (Ure[m][j] * Ure[m][k] + Uim[m][j] * Uim[m][k]);
        }
        A[j][k] = a;
    }
    __syncthreads();

    if (t < 27) {
        int p = t / 9, q = (t / 3) % 3, r = t % 3;
        float csum = 0.f;
        for (int j = 0; j < 8; j++) {
            for (int k = 0; k < 8; k++) {
                int a0 = (j >> 2) & 1, b0 = (k >> 2) & 1;
                int a1 = (j >> 1) & 1, b1 = (k >> 1) & 1;
                int a2 = j & 1,        b2 = k & 1;
                float g0 = (a0 == b0) ? ((p == 0) ? 0.5f : (p == 1) ? (a0 ? -0.5f : 0.5f) : 0.f)
                                      : ((p == 2) ? 0.5f : 0.f);
                float g1 = (a1 == b1) ? ((q == 0) ? 0.5f : (q == 1) ? (a1 ? -0.5f : 0.5f) : 0.f)
                                      : ((q == 2) ? 0.5f : 0.f);
                float g2 = (a2 == b2) ? ((r == 0) ? 0.5f : (r == 1) ? (a2 ? -0.5f : 0.5f) : 0.f)
                                      : ((r == 2) ? 0.5f : 0.f);
                csum += A[j][k] * g0 * g1 * g2;
            }
        }
        d_C[t] = csum;
    }
}

// ---------------------------------------------------------------------------
// mbarrier / bulk-copy helpers
// ---------------------------------------------------------------------------
__device__ __forceinline__ uint32_t smem_u32(const void* p) {
    uint32_t a;
    asm("{ .reg .u64 t; cvta.to.shared.u64 t, %1; cvt.u32.u64 %0, t; }"
        : "=r"(a) : "l"(p));
    return a;
}
__device__ __forceinline__ void mbar_init(uint32_t mbar, uint32_t count) {
    asm volatile("mbarrier.init.shared.b64 [%0], %1;" :: "r"(mbar), "r"(count) : "memory");
}
__device__ __forceinline__ void mbar_expect_tx(uint32_t mbar, uint32_t bytes) {
    asm volatile("mbarrier.arrive.expect_tx.shared.b64 _, [%0], %1;"
                 :: "r"(mbar), "r"(bytes) : "memory");
}
__device__ __forceinline__ void mbar_arrive(uint32_t mbar) {
    asm volatile("mbarrier.arrive.shared.b64 _, [%0];" :: "r"(mbar) : "memory");
}
__device__ __forceinline__ void bulk_ld(uint32_t dst_smem, const void* src, uint32_t bytes,
                                        uint32_t mbar) {
    asm volatile("cp.async.bulk.shared::cta.global.mbarrier::complete_tx::bytes "
                 "[%0], [%1], %2, [%3];"
                 :: "r"(dst_smem), "l"(src), "r"(bytes), "r"(mbar) : "memory");
}
__device__ __forceinline__ void mbar_wait(uint32_t mbar, uint32_t parity) {
    asm volatile(
        "{\n\t"
        ".reg .pred P;\n\t"
        "WAIT_%=:\n\t"
        "mbarrier.try_wait.parity.acquire.cta.shared::cta.b64 P, [%0], %1, 0x989680;\n\t"
        "@P bra DONE_%=;\n\t"
        "bra WAIT_%=;\n\t"
        "DONE_%=:\n\t"
        "}"
        :: "r"(mbar), "r"(parity) : "memory");
}

// ---------------------------------------------------------------------------
// Kernel 2: persistent ring-pipelined eval.
//   - one wave: GRID = 5 blocks/SM * 148 SMs = 740 blocks (40 KB smem each)
//   - each block loops over tiles of 256 rows (8 KB) strided by GRID
//   - 5-stage mbarrier ring keeps up to 5 bulk copies in flight per block
//     continuously -> ~30 MB in flight chip-wide, DRAM never idles.
// ---------------------------------------------------------------------------
static constexpr int BLOCK = 256;
static constexpr int TILE_ROWS = 256;              // rows per tile (8 KB)
static constexpr int TILE_BYTES = TILE_ROWS * 32;
static constexpr int NSTAGE = 5;                   // 40 KB ring
static constexpr int BLOCKS_PER_SM = 5;

__global__ void __launch_bounds__(BLOCK, BLOCKS_PER_SM)
vqc_eval_ring(const float* __restrict__ in, float* __restrict__ out, int ntiles) {
    __shared__ alignas(128) float buf[NSTAGE][TILE_ROWS * 8];
    __shared__ alignas(8) uint64_t full_storage[NSTAGE];
    __shared__ alignas(8) uint64_t empty_storage[NSTAGE];
    __shared__ float cs[27];

    const int t = threadIdx.x;
    const int G = gridDim.x;

    if (t < 27) cs[t] = d_C[t];

    uint32_t fullb[NSTAGE], emptyb[NSTAGE];
    #pragma unroll
    for (int s = 0; s < NSTAGE; s++) {
        fullb[s]  = smem_u32(&full_storage[s]);
        emptyb[s] = smem_u32(&empty_storage[s]);
    }

    if (t == 0) {
        #pragma unroll
        for (int s = 0; s < NSTAGE; s++) {
            mbar_init(fullb[s], 1);          // completed by expect_tx bytes
            mbar_init(emptyb[s], BLOCK);     // all threads arrive after consume
        }
        asm volatile("fence.proxy.async.shared::cta;" ::: "memory");
    }
    __syncthreads();

    // number of tiles this block owns
    int nt = 0;
    for (int j = blockIdx.x; j < ntiles; j += G) nt++;
    if (nt == 0) return;

    // Prologue: fill the ring
    if (t == 0) {
        int pre = (nt < NSTAGE) ? nt : NSTAGE;
        for (int i = 0; i < pre; i++) {
            int tile = blockIdx.x + i * G;
            mbar_expect_tx(fullb[i], TILE_BYTES);
            bulk_ld(smem_u32(&buf[i][0]), in + (size_t)tile * TILE_ROWS * 8,
                    TILE_BYTES, fullb[i]);
        }
    }

    for (int i = 0; i < nt; i++) {
        int stage = i % NSTAGE;
        uint32_t fpar = (uint32_t)((i / NSTAGE) & 1);
        int tile = blockIdx.x + i * G;

        mbar_wait(fullb[stage], fpar);

        // compute: one row per thread (TILE_ROWS == BLOCK)
        float4 x = *reinterpret_cast<const float4*>(&buf[stage][t * 8]);
        float C0, S0, C1, S1, C2, S2;
        __sincosf(x.x, &S0, &C0);
        __sincosf(x.y, &S1, &C1);
        __sincosf(x.z, &S2, &C2);

        float u0[3] = {1.f, C0, S0};
        float u1[3] = {1.f, C1, S1};
        float z = 0.f;
        #pragma unroll
        for (int p = 0; p < 3; p++) {
            #pragma unroll
            for (int q = 0; q < 3; q++) {
                const float* c3 = &cs[p * 9 + q * 3];
                float w = c3[0];
                w = fmaf(c3[1], C2, w);
                w = fmaf(c3[2], S2, w);
                z = fmaf(u0[p] * u1[q], w, z);
            }
        }
        out[(size_t)tile * TILE_ROWS + t] = z;

        mbar_arrive(emptyb[stage]);

        // Refill this stage with tile i + NSTAGE (producer = thread 0)
        if (t == 0) {
            int nx = i + NSTAGE;
            if (nx < nt) {
                uint32_t epar = (uint32_t)((i / NSTAGE) & 1);
                mbar_wait(emptyb[stage], epar);       // all consumers done
                int ntile = blockIdx.x + nx * G;
                mbar_expect_tx(fullb[stage], TILE_BYTES);
                bulk_ld(smem_u32(&buf[stage][0]),
                        in + (size_t)ntile * TILE_ROWS * 8, TILE_BYTES, fullb[stage]);
            }
        }
    }
}

// ---------------------------------------------------------------------------
// Tail kernel (plain LDG) for B not divisible by TILE_ROWS.
// ---------------------------------------------------------------------------
__global__ void vqc_eval_tail(const float4* __restrict__ in, float* __restrict__ out,
                              int start, int B) {
    __shared__ float cs[27];
    if (threadIdx.x < 27) cs[threadIdx.x] = d_C[threadIdx.x];
    __syncthreads();

    int i = start + blockIdx.x * blockDim.x + threadIdx.x;
    if (i < B) {
        float4 x = in[(size_t)i * 2];
        float C0, S0, C1, S1, C2, S2;
        __sincosf(x.x, &S0, &C0);
        __sincosf(x.y, &S1, &C1);
        __sincosf(x.z, &S2, &C2);
        float u0[3] = {1.f, C0, S0};
        float u1[3] = {1.f, C1, S1};
        float z = 0.f;
        #pragma unroll
        for (int p = 0; p < 3; p++) {
            #pragma unroll
            for (int q = 0; q < 3; q++) {
                const float* c3 = &cs[p * 9 + q * 3];
                float w = c3[0];
                w = fmaf(c3[1], C2, w);
                w = fmaf(c3[2], S2, w);
                z = fmaf(u0[p] * u1[q], w, z);
            }
        }
        out[i] = z;
    }
}

extern "C" void kernel_launch(void* const* d_in, const int* in_sizes, int n_in,
                              void* d_out, int out_size) {
    const float* inputs = (const float*)d_in[0];   // (B, 8) float32
    const float* qw     = (const float*)d_in[1];   // (3, 3, 2) float32
    float* out          = (float*)d_out;           // (B, 1) float32

    int B = in_sizes[0] / 8;

    build_coeffs<<<1, 64>>>(qw);

    int ntiles = B / TILE_ROWS;                    // 4096 for B = 2^20
    if (ntiles > 0) {
        int grid = 148 * BLOCKS_PER_SM;            // 740: single persistent wave
        if (grid > ntiles) grid = ntiles;
        vqc_eval_ring<<<grid, BLOCK>>>(inputs, out, ntiles);
    }

    int done = ntiles * TILE_ROWS;
    int tail = B - done;
    if (tail > 0) {
        int tgrid = (tail + BLOCK - 1) / BLOCK;
        vqc_eval_tail<<<tgrid, BLOCK>>>((const float4*)inputs, out, done, B);
    }
}

// round 8
// speedup vs baseline: 1.4090x; 1.4090x over previous
#include <cuda_runtime.h>
#include <cstdint>

// z = sum_{p,q,r} C[p*9+q*3+r] * u0_p * u1_q * u2_r,  u_i = (1, cos x_i, sin x_i)
__device__ float d_C[27];

// ---------------------------------------------------------------------------
// Kernel 1: build the 27 trilinear coefficients from q_weights (18 floats).
// ---------------------------------------------------------------------------
__global__ void build_coeffs(const float* __restrict__ qw) {
    __shared__ float Ure[8][8];
    __shared__ float Uim[8][8];
    __shared__ float A[8][8];

    int t = threadIdx.x;

    if (t < 8) {
        const int j = t;
        float sr[8], si[8];
        #pragma unroll
        for (int m = 0; m < 8; m++) { sr[m] = 0.f; si[m] = 0.f; }
        sr[j] = 1.0f;

        for (int l = 0; l < 3; l++) {
            #pragma unroll
            for (int q = 0; q < 3; q++) {
                float ty = qw[(l * 3 + q) * 2 + 0];
                float tz = qw[(l * 3 + q) * 2 + 1];
                int bit = 4 >> q;

                float c, s;
                __sincosf(0.5f * ty, &s, &c);
                #pragma unroll
                for (int m = 0; m < 8; m++) {
                    if (m & bit) continue;
                    int m1 = m | bit;
                    float ar = sr[m],  ai = si[m];
                    float br = sr[m1], bi = si[m1];
                    sr[m]  = c * ar - s * br;  si[m]  = c * ai - s * bi;
                    sr[m1] = s * ar + c * br;  si[m1] = s * ai + c * bi;
                }

                float cz, sz;
                __sincosf(0.5f * tz, &sz, &cz);
                #pragma unroll
                for (int m = 0; m < 8; m++) {
                    float ar = sr[m], ai = si[m];
                    if (m & bit) { sr[m] = cz * ar - sz * ai; si[m] = cz * ai + sz * ar; }
                    else         { sr[m] = cz * ar + sz * ai; si[m] = cz * ai - sz * ar; }
                }
            }
            #pragma unroll
            for (int m = 4; m < 6; m++) {           // CNOT01: swap (4,6),(5,7)
                int m1 = m | 2; float tmp;
                tmp = sr[m]; sr[m] = sr[m1]; sr[m1] = tmp;
                tmp = si[m]; si[m] = si[m1]; si[m1] = tmp;
            }
            #pragma unroll
            for (int m = 2; m < 8; m += 4) {        // CNOT12: swap (2,3),(6,7)
                int m1 = m | 1; float tmp;
                tmp = sr[m]; sr[m] = sr[m1]; sr[m1] = tmp;
                tmp = si[m]; si[m] = si[m1]; si[m1] = tmp;
            }
        }
        #pragma unroll
        for (int m = 0; m < 8; m++) { Ure[m][j] = sr[m]; Uim[m][j] = si[m]; }
    }
    __syncthreads();

    if (t < 64) {
        int j = t >> 3, k = t & 7;
        float a = 0.f;
        #pragma unroll
        for (int m = 0; m < 8; m++) {
            float sgn = (m & 4) ? -1.f : 1.f;
            a += sgn * (Ure[m][j] * Ure[m][k] + Uim[m][j] * Uim[m][k]);
        }
        A[j][k] = a;
    }
    __syncthreads();

    if (t < 27) {
        int p = t / 9, q = (t / 3) % 3, r = t % 3;
        float csum = 0.f;
        for (int j = 0; j < 8; j++) {
            for (int k = 0; k < 8; k++) {
                int a0 = (j >> 2) & 1, b0 = (k >> 2) & 1;
                int a1 = (j >> 1) & 1, b1 = (k >> 1) & 1;
                int a2 = j & 1,        b2 = k & 1;
                float g0 = (a0 == b0) ? ((p == 0) ? 0.5f : (p == 1) ? (a0 ? -0.5f : 0.5f) : 0.f)
                                      : ((p == 2) ? 0.5f : 0.f);
                float g1 = (a1 == b1) ? ((q == 0) ? 0.5f : (q == 1) ? (a1 ? -0.5f : 0.5f) : 0.f)
                                      : ((q == 2) ? 0.5f : 0.f);
                float g2 = (a2 == b2) ? ((r == 0) ? 0.5f : (r == 1) ? (a2 ? -0.5f : 0.5f) : 0.f)
                                      : ((r == 2) ? 0.5f : 0.f);
                csum += A[j][k] * g0 * g1 * g2;
            }
        }
        d_C[t] = csum;
    }
}

// ---------------------------------------------------------------------------
// Kernel 2: evaluate, launched with Programmatic Stream Serialization.
// All 8 input loads are issued BEFORE cudaGridDependencySynchronize(), so
// CTA launch + DRAM latency overlap build_coeffs' execution. d_C is read
// only after the dependency sync.
// ---------------------------------------------------------------------------
static constexpr int SPT = 8;
static constexpr int BLOCK = 256;

__global__ void __launch_bounds__(BLOCK) vqc_eval(const float4* __restrict__ in,
                                                  float* __restrict__ out, int B) {
    const int T = gridDim.x * BLOCK;
    const int t = blockIdx.x * BLOCK + threadIdx.x;

    // Front-batch ALL loads — independent of build_coeffs' output.
    float4 x[SPT];
    #pragma unroll
    for (int k = 0; k < SPT; k++) {
        int i = t + k * T;
        i = (i < B) ? i : (B - 1);
        x[k] = in[(size_t)i * 2];     // first 16B of the 32B row
    }

    // Wait for build_coeffs to complete (PDL), then read coefficients.
    cudaGridDependencySynchronize();

    __shared__ float cs[27];
    if (threadIdx.x < 27) cs[threadIdx.x] = d_C[threadIdx.x];
    __syncthreads();

    #pragma unroll
    for (int k = 0; k < SPT; k++) {
        float C0, S0, C1, S1, C2, S2;
        __sincosf(x[k].x, &S0, &C0);
        __sincosf(x[k].y, &S1, &C1);
        __sincosf(x[k].z, &S2, &C2);

        float u0[3] = {1.f, C0, S0};
        float u1[3] = {1.f, C1, S1};
        float z = 0.f;
        #pragma unroll
        for (int p = 0; p < 3; p++) {
            #pragma unroll
            for (int q = 0; q < 3; q++) {
                const float* c3 = &cs[p * 9 + q * 3];
                float w = c3[0];
                w = fmaf(c3[1], C2, w);
                w = fmaf(c3[2], S2, w);
                z = fmaf(u0[p] * u1[q], w, z);
            }
        }
        int i = t + k * T;
        if (i < B) out[i] = z;
    }
}

extern "C" void kernel_launch(void* const* d_in, const int* in_sizes, int n_in,
                              void* d_out, int out_size) {
    const float* inputs = (const float*)d_in[0];   // (B, 8) float32
    const float* qw     = (const float*)d_in[1];   // (3, 3, 2) float32
    float* out          = (float*)d_out;           // (B, 1) float32

    int B = in_sizes[0] / 8;

    build_coeffs<<<1, 64>>>(qw);

    int grid = (B + BLOCK * SPT - 1) / (BLOCK * SPT);   // 512 for B = 2^20

    cudaLaunchConfig_t cfg = {};
    cfg.gridDim = dim3(grid);
    cfg.blockDim = dim3(BLOCK);
    cfg.dynamicSmemBytes = 0;
    cudaLaunchAttribute attr[1];
    attr[0].id = cudaLaunchAttributeProgrammaticStreamSerialization;
    attr[0].val.programmaticStreamSerializationAllowed = 1;
    cfg.attrs = attr;
    cfg.numAttrs = 1;

    cudaLaunchKernelEx(&cfg, vqc_eval, (const float4*)inputs, out, B);
}